// round 11
// baseline (speedup 1.0000x reference)
#include <cuda_runtime.h>
#include <cuda_bf16.h>

#define BATCH   32768
#define HID     128
#define INF     784
#define NCLS    10
#define TSTEPS  20

#define DECAYF  0.25f
#define THRESHF 1.0f
#define EPSM    2e-4f
#define EPS2    2e-4f

#define KCHUNKS (INF / 16)      // 49
#define FIXCAP  (1 << 21)
#define FIX2CAP (1 << 20)

// Scratch (device globals)
__device__ float    g_c2[(size_t)TSTEPS * BATCH * NCLS];
__device__ unsigned g_fix_list[FIXCAP];
__device__ unsigned g_fix_cnt;
__device__ unsigned g_fix2_list[FIX2CAP];
__device__ unsigned g_fix2_cnt;
__device__ __align__(16) unsigned g_bits[(size_t)TSTEPS * BATCH * 4];  // 10.5MB bitpack
__device__ float    g_lutn[32 * 16 * 12];                              // nibble LUT
__device__ __align__(16) unsigned short g_w1a[HID * INF];   // bf16 hi plane
__device__ __align__(16) unsigned short g_w1b[HID * INF];   // bf16 lo plane

// ---------------------------------------------------------------------------
__device__ __forceinline__ void split2(float v, unsigned short& h0, unsigned short& h1)
{
    __nv_bfloat16 b0 = __float2bfloat16_rn(v);
    float r = v - __bfloat162float(b0);
    __nv_bfloat16 b1 = __float2bfloat16_rn(r);
    h0 = __bfloat16_as_ushort(b0);
    h1 = __bfloat16_as_ushort(b1);
}

__device__ __forceinline__ void mma_bf16(float* d, const unsigned* a, const unsigned* b)
{
    asm volatile(
        "mma.sync.aligned.m16n8k16.row.col.f32.bf16.bf16.f32 "
        "{%0,%1,%2,%3}, {%4,%5,%6,%7}, {%8,%9}, {%0,%1,%2,%3};"
        : "+f"(d[0]), "+f"(d[1]), "+f"(d[2]), "+f"(d[3])
        : "r"(a[0]), "r"(a[1]), "r"(a[2]), "r"(a[3]), "r"(b[0]), "r"(b[1]));
}

__global__ void k0_init(const float* __restrict__ W1)
{
    if (blockIdx.x == 0 && threadIdx.x == 0) { g_fix_cnt = 0; g_fix2_cnt = 0; }
    int i = blockIdx.x * blockDim.x + threadIdx.x;
    if (i < HID * INF) {
        unsigned short h0, h1;
        split2(W1[i], h0, h1);
        g_w1a[i] = h0;
        g_w1b[i] = h1;
    }
}

// Build nibble LUT: entry (ni, pat): sum over set bits b (ascending) of W2[o][ni*4+b]
__global__ void k_lut_build(const float* __restrict__ W2)
{
    int idx = blockIdx.x * blockDim.x + threadIdx.x;   // 0..511
    if (idx >= 32 * 16) return;
    int ni = idx >> 4;
    int pat = idx & 15;
    float* e = &g_lutn[idx * 12];
    #pragma unroll
    for (int o = 0; o < NCLS; o++) {
        float a = 0.0f;
        #pragma unroll
        for (int b = 0; b < 4; b++)
            if (pat & (1 << b)) a += W2[o * HID + ni * 4 + b];
        e[o] = a;
    }
    e[10] = 0.0f; e[11] = 0.0f;
}

// ---------------------------------------------------------------------------
// K1: R5 tensor GEMM1 + LIF + margin tracking, plus bitpacked spike output.
// ---------------------------------------------------------------------------
#define ASTRIDE 24

__global__ __launch_bounds__(256) void k1_mma(
    const float* __restrict__ x, const float* __restrict__ b1,
    float* __restrict__ out_spk)
{
    __shared__ unsigned short As[2][2][64  * ASTRIDE];
    __shared__ unsigned short Bs[2][2][128 * ASTRIDE];

    const int tid  = threadIdx.x;
    const int lane = tid & 31;
    const int wid  = tid >> 5;
    const int g    = lane >> 2;
    const int tg   = lane & 3;
    const int wm   = wid >> 2;
    const int wn   = wid & 3;
    const int m0   = blockIdx.x * 64;

    const int sm_r = tid >> 2;
    const int skq  = (tid & 3) * 4;
    const int bn   = tid >> 1;
    const int bkh  = (tid & 1) * 8;

    float acc[2][4][4];
    #pragma unroll
    for (int mt = 0; mt < 2; mt++)
        #pragma unroll
        for (int nt = 0; nt < 4; nt++)
            #pragma unroll
            for (int r = 0; r < 4; r++) acc[mt][nt][r] = 0.0f;

    // prologue: stage chunk 0 into buf 0
    {
        float4 ax = *reinterpret_cast<const float4*>(&x[(size_t)(m0 + sm_r) * INF + skq]);
        float av[4] = {ax.x, ax.y, ax.z, ax.w};
        unsigned short p0[4], p1[4];
        #pragma unroll
        for (int i = 0; i < 4; i++) split2(av[i], p0[i], p1[i]);
        *reinterpret_cast<uint2*>(&As[0][0][sm_r * ASTRIDE + skq]) = *reinterpret_cast<uint2*>(p0);
        *reinterpret_cast<uint2*>(&As[0][1][sm_r * ASTRIDE + skq]) = *reinterpret_cast<uint2*>(p1);

        uint4 va = *reinterpret_cast<const uint4*>(&g_w1a[bn * INF + bkh]);
        uint4 vb = *reinterpret_cast<const uint4*>(&g_w1b[bn * INF + bkh]);
        *reinterpret_cast<uint4*>(&Bs[0][0][bn * ASTRIDE + bkh]) = va;
        *reinterpret_cast<uint4*>(&Bs[0][1][bn * ASTRIDE + bkh]) = vb;
    }
    __syncthreads();

    int buf = 0;
    for (int kc = 0; kc < KCHUNKS; kc++) {
        float4 pax;
        uint4 pba, pbb;
        if (kc < KCHUNKS - 1) {
            int k0 = (kc + 1) * 16;
            pax = *reinterpret_cast<const float4*>(&x[(size_t)(m0 + sm_r) * INF + k0 + skq]);
            pba = *reinterpret_cast<const uint4*>(&g_w1a[bn * INF + k0 + bkh]);
            pbb = *reinterpret_cast<const uint4*>(&g_w1b[bn * INF + k0 + bkh]);
        }

        unsigned aF[2][2][4];
        #pragma unroll
        for (int s = 0; s < 2; s++)
            #pragma unroll
            for (int mt = 0; mt < 2; mt++) {
                const unsigned short* ap = &As[buf][s][(wm * 32 + mt * 16) * ASTRIDE];
                aF[s][mt][0] = *reinterpret_cast<const unsigned*>(&ap[(g)     * ASTRIDE + tg * 2]);
                aF[s][mt][1] = *reinterpret_cast<const unsigned*>(&ap[(g + 8) * ASTRIDE + tg * 2]);
                aF[s][mt][2] = *reinterpret_cast<const unsigned*>(&ap[(g)     * ASTRIDE + tg * 2 + 8]);
                aF[s][mt][3] = *reinterpret_cast<const unsigned*>(&ap[(g + 8) * ASTRIDE + tg * 2 + 8]);
            }
        unsigned bF[2][4][2];
        #pragma unroll
        for (int s = 0; s < 2; s++)
            #pragma unroll
            for (int nt = 0; nt < 4; nt++) {
                const unsigned short* bp = &Bs[buf][s][(wn * 32 + nt * 8 + g) * ASTRIDE];
                bF[s][nt][0] = *reinterpret_cast<const unsigned*>(&bp[tg * 2]);
                bF[s][nt][1] = *reinterpret_cast<const unsigned*>(&bp[tg * 2 + 8]);
            }

        #pragma unroll
        for (int p = 0; p < 3; p++) {
            const int PI[3] = {0, 0, 1};
            const int PJ[3] = {0, 1, 0};
            int i = PI[p], j = PJ[p];
            #pragma unroll
            for (int mt = 0; mt < 2; mt++)
                #pragma unroll
                for (int nt = 0; nt < 4; nt++)
                    mma_bf16(acc[mt][nt], aF[i][mt], bF[j][nt]);
        }

        if (kc < KCHUNKS - 1) {
            int ob = buf ^ 1;
            float av[4] = {pax.x, pax.y, pax.z, pax.w};
            unsigned short p0[4], p1[4];
            #pragma unroll
            for (int i = 0; i < 4; i++) split2(av[i], p0[i], p1[i]);
            *reinterpret_cast<uint2*>(&As[ob][0][sm_r * ASTRIDE + skq]) = *reinterpret_cast<uint2*>(p0);
            *reinterpret_cast<uint2*>(&As[ob][1][sm_r * ASTRIDE + skq]) = *reinterpret_cast<uint2*>(p1);
            *reinterpret_cast<uint4*>(&Bs[ob][0][bn * ASTRIDE + bkh]) = pba;
            *reinterpret_cast<uint4*>(&Bs[ob][1][bn * ASTRIDE + bkh]) = pbb;
        }
        __syncthreads();
        buf ^= 1;
    }

    // ---- epilogue: + b1, LIF with margin tracking, float + bitpack stores ----
    float cur[2][4][4];
    #pragma unroll
    for (int nt = 0; nt < 4; nt++) {
        float2 bv = *reinterpret_cast<const float2*>(&b1[wn * 32 + nt * 8 + tg * 2]);
        #pragma unroll
        for (int mt = 0; mt < 2; mt++) {
            cur[mt][nt][0] = acc[mt][nt][0] + bv.x;
            cur[mt][nt][1] = acc[mt][nt][1] + bv.y;
            cur[mt][nt][2] = acc[mt][nt][2] + bv.x;
            cur[mt][nt][3] = acc[mt][nt][3] + bv.y;
        }
    }

    float mem[2][4][4];
    unsigned badm[2][4];
    #pragma unroll
    for (int mt = 0; mt < 2; mt++)
        #pragma unroll
        for (int nt = 0; nt < 4; nt++) {
            badm[mt][nt] = 0u;
            #pragma unroll
            for (int r = 0; r < 4; r++) mem[mt][nt][r] = 0.0f;
        }

    for (int t = 0; t < TSTEPS; t++) {
        float* pt = out_spk + (size_t)t * ((size_t)BATCH * HID);
        #pragma unroll
        for (int mt = 0; mt < 2; mt++) {
            int r0 = m0 + wm * 32 + mt * 16 + g;
            unsigned mA = 0u, mB = 0u;
            #pragma unroll
            for (int nt = 0; nt < 4; nt++) {
                int n = wn * 32 + nt * 8 + tg * 2;
                float s[4];
                #pragma unroll
                for (int r = 0; r < 4; r++) {
                    float m = fmaf(mem[mt][nt][r], DECAYF, cur[mt][nt][r]);
                    if (fabsf(m - THRESHF) < EPSM) badm[mt][nt] |= (1u << r);
                    s[r] = (m > THRESHF) ? 1.0f : 0.0f;
                    mem[mt][nt][r] = (s[r] != 0.0f) ? 0.0f : m;
                }
                float2 v0 = {s[0], s[1]};
                float2 v1 = {s[2], s[3]};
                *reinterpret_cast<float2*>(&pt[(size_t)r0 * HID + n])       = v0;
                *reinterpret_cast<float2*>(&pt[(size_t)(r0 + 8) * HID + n]) = v1;
                unsigned sh = nt * 8 + tg * 2;
                mA |= (((s[0] != 0.0f) ? 1u : 0u) | ((s[1] != 0.0f) ? 2u : 0u)) << sh;
                mB |= (((s[2] != 0.0f) ? 1u : 0u) | ((s[3] != 0.0f) ? 2u : 0u)) << sh;
            }
            // OR-combine across the 4 tg lanes (lanes differ in bits 0-1)
            mA |= __shfl_xor_sync(0xffffffffu, mA, 1);
            mA |= __shfl_xor_sync(0xffffffffu, mA, 2);
            mB |= __shfl_xor_sync(0xffffffffu, mB, 1);
            mB |= __shfl_xor_sync(0xffffffffu, mB, 2);
            if (tg == 0) {
                g_bits[((size_t)t * BATCH + r0) * 4 + wn]     = mA;
                g_bits[((size_t)t * BATCH + r0 + 8) * 4 + wn] = mB;
            }
        }
    }

    #pragma unroll
    for (int mt = 0; mt < 2; mt++)
        #pragma unroll
        for (int nt = 0; nt < 4; nt++)
            if (badm[mt][nt]) {
                #pragma unroll
                for (int r = 0; r < 4; r++)
                    if (badm[mt][nt] & (1u << r)) {
                        int row = m0 + wm * 32 + mt * 16 + g + ((r >> 1) ? 8 : 0);
                        int col = wn * 32 + nt * 8 + tg * 2 + (r & 1);
                        unsigned pos = atomicAdd(&g_fix_cnt, 1u);
                        if (pos < FIXCAP)
                            g_fix_list[pos] = (unsigned)(row * HID + col);
                    }
            }
}

// ---------------------------------------------------------------------------
// K1b fixup: exact recompute of spikes (bitwise R1 recipe) + bitpack patch.
// ---------------------------------------------------------------------------
__global__ __launch_bounds__(128) void k1_fixup(
    const float* __restrict__ x, const float* __restrict__ W1,
    const float* __restrict__ b1, float* __restrict__ out_spk)
{
    const unsigned cnt = min(*(volatile unsigned*)&g_fix_cnt, (unsigned)FIXCAP);
    const int stride = gridDim.x * blockDim.x;

    for (unsigned i = blockIdx.x * blockDim.x + threadIdx.x; i < cnt; i += stride) {
        unsigned idx = g_fix_list[i];
        int b = idx >> 7;
        int j = idx & (HID - 1);

        const float* xr = x  + (size_t)b * INF;
        const float* wr = W1 + (size_t)j * INF;
        float a = 0.0f;
        for (int k = 0; k < INF; k++)
            a = fmaf(__ldg(&xr[k]), __ldg(&wr[k]), a);
        float curv = a + __ldg(&b1[j]);

        const int wordi = j >> 5;
        const unsigned bit = 1u << (j & 31);

        float m = 0.0f;
        for (int t = 0; t < TSTEPS; t++) {
            m = fmaf(m, DECAYF, curv);
            float s = (m > THRESHF) ? 1.0f : 0.0f;
            out_spk[(size_t)t * ((size_t)BATCH * HID) + idx] = s;
            unsigned* bp = &g_bits[((size_t)t * BATCH + b) * 4 + wordi];
            if (s != 0.0f) atomicOr(bp, bit);
            else           atomicAnd(bp, ~bit);
            m = (s != 0.0f) ? 0.0f : m;
        }
    }
}

// ---------------------------------------------------------------------------
// K3: c2 via nibble LUT over bitpacked spikes. One thread per row.
// ---------------------------------------------------------------------------
__global__ __launch_bounds__(256) void k3_lut()
{
    __shared__ float slut[32 * 16 * 12];   // 24KB
    const int tid = threadIdx.x;
    #pragma unroll
    for (int i = tid; i < 32 * 16 * 12; i += 256) slut[i] = g_lutn[i];
    __syncthreads();

    const size_t row = (size_t)blockIdx.x * 256 + tid;   // over TSTEPS*BATCH
    uint4 bw = *reinterpret_cast<const uint4*>(&g_bits[row * 4]);
    unsigned wds[4] = {bw.x, bw.y, bw.z, bw.w};

    float acc[NCLS];
    #pragma unroll
    for (int o = 0; o < NCLS; o++) acc[o] = 0.0f;

    #pragma unroll
    for (int ni = 0; ni < 32; ni++) {
        unsigned nib = (wds[ni >> 3] >> ((ni & 7) * 4)) & 15u;
        const float* e = &slut[(ni * 16 + (int)nib) * 12];
        float4 e0 = *reinterpret_cast<const float4*>(e);
        float4 e1 = *reinterpret_cast<const float4*>(e + 4);
        float2 e2 = *reinterpret_cast<const float2*>(e + 8);
        acc[0] += e0.x; acc[1] += e0.y; acc[2] += e0.z; acc[3] += e0.w;
        acc[4] += e1.x; acc[5] += e1.y; acc[6] += e1.z; acc[7] += e1.w;
        acc[8] += e2.x; acc[9] += e2.y;
    }

    float* cp = &g_c2[row * NCLS];
    #pragma unroll
    for (int o = 0; o < NCLS; o++) cp[o] = acc[o];
}

// ---------------------------------------------------------------------------
// K4: layer-2 recurrence + output, with margin flagging (c2 is approximate).
// ---------------------------------------------------------------------------
__global__ __launch_bounds__(256) void k4_lif2(
    const float* __restrict__ b2, float* __restrict__ outp)
{
    const int id = blockIdx.x * blockDim.x + threadIdx.x;   // b*NCLS+o
    const int o = id % NCLS;
    const float bias = __ldg(&b2[o]);

    float mem = 0.0f, acc = 0.0f;
    bool flag = false;
    #pragma unroll
    for (int t = 0; t < TSTEPS; t++) {
        float v = fmaf(mem, DECAYF, g_c2[(size_t)t * (BATCH * NCLS) + id]);
        v = v + bias;
        if (fabsf(v - THRESHF) < EPS2) flag = true;
        float s = (v > THRESHF) ? 1.0f : 0.0f;
        acc += s;
        mem = (s != 0.0f) ? 0.0f : v;
    }
    outp[id] = acc;

    if (flag) {
        unsigned pos = atomicAdd(&g_fix2_cnt, 1u);
        if (pos < FIX2CAP) g_fix2_list[pos] = (unsigned)id;
    }
}

// ---------------------------------------------------------------------------
// K4fix: for flagged (b,o): exact c2 chain (bitwise R1 k3 recipe, ascending j)
// from float spikes, exact LIF, overwrite output element.
// ---------------------------------------------------------------------------
__global__ __launch_bounds__(128) void k4_fix(
    const float* __restrict__ spk, const float* __restrict__ W2,
    const float* __restrict__ b2, float* __restrict__ outp)
{
    const unsigned cnt = min(*(volatile unsigned*)&g_fix2_cnt, (unsigned)FIX2CAP);
    const int stride = gridDim.x * blockDim.x;

    for (unsigned i = blockIdx.x * blockDim.x + threadIdx.x; i < cnt; i += stride) {
        unsigned id = g_fix2_list[i];
        int b = id / NCLS;
        int o = id - b * NCLS;
        const float* wr = W2 + (size_t)o * HID;
        const float bias = __ldg(&b2[o]);

        float mem = 0.0f, acc = 0.0f;
        for (int t = 0; t < TSTEPS; t++) {
            const float* sr = spk + (size_t)t * ((size_t)BATCH * HID) + (size_t)b * HID;
            float a = 0.0f;
            for (int j = 0; j < HID; j++)
                a = fmaf(__ldg(&sr[j]), __ldg(&wr[j]), a);
            float v = fmaf(mem, DECAYF, a);
            v = v + bias;
            float s = (v > THRESHF) ? 1.0f : 0.0f;
            acc += s;
            mem = (s != 0.0f) ? 0.0f : v;
        }
        outp[id] = acc;
    }
}

// ---------------------------------------------------------------------------
extern "C" void kernel_launch(void* const* d_in, const int* in_sizes, int n_in,
                              void* d_out, int out_size)
{
    const float* x  = (const float*)d_in[0];
    const float* W1 = (const float*)d_in[1];
    const float* b1 = (const float*)d_in[2];
    const float* W2 = (const float*)d_in[3];
    const float* b2 = (const float*)d_in[4];
    float* out = (float*)d_out;

    float* out_output = out;
    float* out_spk    = out + (size_t)BATCH * NCLS;

    k0_init<<<(HID * INF + 255) / 256, 256>>>(W1);
    k_lut_build<<<2, 256>>>(W2);
    k1_mma<<<BATCH / 64, 256>>>(x, b1, out_spk);
    k1_fixup<<<256, 128>>>(x, W1, b1, out_spk);
    k3_lut<<<(TSTEPS * BATCH) / 256, 256>>>();
    k4_lif2<<<(BATCH * NCLS) / 256, 256>>>(b2, out_output);
    k4_fix<<<256, 128>>>(out_spk, W2, b2, out_output);
}

// round 12
// speedup vs baseline: 1.3362x; 1.3362x over previous
#include <cuda_runtime.h>
#include <cuda_bf16.h>

#define BATCH   32768
#define HID     128
#define INF     784
#define NCLS    10
#define TSTEPS  20

#define DECAYF  0.25f
#define THRESHF 1.0f
#define EPSM    2e-4f

#define KCHUNKS (INF / 16)      // 49
#define FIXCAP  (1 << 21)

// Scratch (device globals)
__device__ float    g_c2[(size_t)TSTEPS * BATCH * NCLS];
__device__ unsigned g_fix_list[FIXCAP];
__device__ unsigned g_fix_cnt;
__device__ __align__(16) unsigned short g_w1a[HID * INF];   // bf16 hi plane
__device__ __align__(16) unsigned short g_w1b[HID * INF];   // bf16 lo plane

// ---------------------------------------------------------------------------
__device__ __forceinline__ void split2(float v, unsigned short& h0, unsigned short& h1)
{
    __nv_bfloat16 b0 = __float2bfloat16_rn(v);
    float r = v - __bfloat162float(b0);
    __nv_bfloat16 b1 = __float2bfloat16_rn(r);
    h0 = __bfloat16_as_ushort(b0);
    h1 = __bfloat16_as_ushort(b1);
}

__device__ __forceinline__ void mma_bf16(float* d, const unsigned* a, const unsigned* b)
{
    asm volatile(
        "mma.sync.aligned.m16n8k16.row.col.f32.bf16.bf16.f32 "
        "{%0,%1,%2,%3}, {%4,%5,%6,%7}, {%8,%9}, {%0,%1,%2,%3};"
        : "+f"(d[0]), "+f"(d[1]), "+f"(d[2]), "+f"(d[3])
        : "r"(a[0]), "r"(a[1]), "r"(a[2]), "r"(a[3]), "r"(b[0]), "r"(b[1]));
}

__global__ void k0_init(const float* __restrict__ W1)
{
    if (blockIdx.x == 0 && threadIdx.x == 0) g_fix_cnt = 0;
    int i = blockIdx.x * blockDim.x + threadIdx.x;
    if (i < HID * INF) {
        unsigned short h0, h1;
        split2(W1[i], h0, h1);
        g_w1a[i] = h0;
        g_w1b[i] = h1;
    }
}

// ---------------------------------------------------------------------------
// K1: cur1 via bf16x2-split (3 tensor-core products), fused LIF epilogue with
// margin tracking. Tile M=64 x N=128, 256 threads = 8 warps (2m x 4n).
// (verbatim R5 — proven)
// ---------------------------------------------------------------------------
#define ASTRIDE 24

__global__ __launch_bounds__(256) void k1_mma(
    const float* __restrict__ x, const float* __restrict__ b1,
    float* __restrict__ out_spk)
{
    __shared__ unsigned short As[2][2][64  * ASTRIDE];
    __shared__ unsigned short Bs[2][2][128 * ASTRIDE];

    const int tid  = threadIdx.x;
    const int lane = tid & 31;
    const int wid  = tid >> 5;
    const int g    = lane >> 2;
    const int tg   = lane & 3;
    const int wm   = wid >> 2;
    const int wn   = wid & 3;
    const int m0   = blockIdx.x * 64;

    const int sm  = tid >> 2;           // A stage row 0..63
    const int skq = (tid & 3) * 4;      // A stage k 0,4,8,12
    const int bn  = tid >> 1;           // B stage n 0..127
    const int bkh = (tid & 1) * 8;      // B stage k half

    float acc[2][4][4];
    #pragma unroll
    for (int mt = 0; mt < 2; mt++)
        #pragma unroll
        for (int nt = 0; nt < 4; nt++)
            #pragma unroll
            for (int r = 0; r < 4; r++) acc[mt][nt][r] = 0.0f;

    // ---- prologue: stage chunk 0 into buf 0 ----
    {
        float4 ax = *reinterpret_cast<const float4*>(&x[(size_t)(m0 + sm) * INF + skq]);
        float av[4] = {ax.x, ax.y, ax.z, ax.w};
        unsigned short p0[4], p1[4];
        #pragma unroll
        for (int i = 0; i < 4; i++) split2(av[i], p0[i], p1[i]);
        *reinterpret_cast<uint2*>(&As[0][0][sm * ASTRIDE + skq]) = *reinterpret_cast<uint2*>(p0);
        *reinterpret_cast<uint2*>(&As[0][1][sm * ASTRIDE + skq]) = *reinterpret_cast<uint2*>(p1);

        uint4 va = *reinterpret_cast<const uint4*>(&g_w1a[bn * INF + bkh]);
        uint4 vb = *reinterpret_cast<const uint4*>(&g_w1b[bn * INF + bkh]);
        *reinterpret_cast<uint4*>(&Bs[0][0][bn * ASTRIDE + bkh]) = va;
        *reinterpret_cast<uint4*>(&Bs[0][1][bn * ASTRIDE + bkh]) = vb;
    }
    __syncthreads();

    int buf = 0;
    for (int kc = 0; kc < KCHUNKS; kc++) {
        // prefetch next chunk
        float4 pax;
        uint4 pba, pbb;
        if (kc < KCHUNKS - 1) {
            int k0 = (kc + 1) * 16;
            pax = *reinterpret_cast<const float4*>(&x[(size_t)(m0 + sm) * INF + k0 + skq]);
            pba = *reinterpret_cast<const uint4*>(&g_w1a[bn * INF + k0 + bkh]);
            pbb = *reinterpret_cast<const uint4*>(&g_w1b[bn * INF + k0 + bkh]);
        }

        // fragments
        unsigned aF[2][2][4];
        #pragma unroll
        for (int s = 0; s < 2; s++)
            #pragma unroll
            for (int mt = 0; mt < 2; mt++) {
                const unsigned short* ab = &As[buf][s][(wm * 32 + mt * 16) * ASTRIDE];
                aF[s][mt][0] = *reinterpret_cast<const unsigned*>(&ab[(g)     * ASTRIDE + tg * 2]);
                aF[s][mt][1] = *reinterpret_cast<const unsigned*>(&ab[(g + 8) * ASTRIDE + tg * 2]);
                aF[s][mt][2] = *reinterpret_cast<const unsigned*>(&ab[(g)     * ASTRIDE + tg * 2 + 8]);
                aF[s][mt][3] = *reinterpret_cast<const unsigned*>(&ab[(g + 8) * ASTRIDE + tg * 2 + 8]);
            }
        unsigned bF[2][4][2];
        #pragma unroll
        for (int s = 0; s < 2; s++)
            #pragma unroll
            for (int nt = 0; nt < 4; nt++) {
                const unsigned short* bb = &Bs[buf][s][(wn * 32 + nt * 8 + g) * ASTRIDE];
                bF[s][nt][0] = *reinterpret_cast<const unsigned*>(&bb[tg * 2]);
                bF[s][nt][1] = *reinterpret_cast<const unsigned*>(&bb[tg * 2 + 8]);
            }

        // 3 split-products: a0b0, a0b1, a1b0
        #pragma unroll
        for (int p = 0; p < 3; p++) {
            const int PI[3] = {0, 0, 1};
            const int PJ[3] = {0, 1, 0};
            int i = PI[p], j = PJ[p];
            #pragma unroll
            for (int mt = 0; mt < 2; mt++)
                #pragma unroll
                for (int nt = 0; nt < 4; nt++)
                    mma_bf16(acc[mt][nt], aF[i][mt], bF[j][nt]);
        }

        // stage prefetched chunk into other buffer
        if (kc < KCHUNKS - 1) {
            int ob = buf ^ 1;
            float av[4] = {pax.x, pax.y, pax.z, pax.w};
            unsigned short p0[4], p1[4];
            #pragma unroll
            for (int i = 0; i < 4; i++) split2(av[i], p0[i], p1[i]);
            *reinterpret_cast<uint2*>(&As[ob][0][sm * ASTRIDE + skq]) = *reinterpret_cast<uint2*>(p0);
            *reinterpret_cast<uint2*>(&As[ob][1][sm * ASTRIDE + skq]) = *reinterpret_cast<uint2*>(p1);
            *reinterpret_cast<uint4*>(&Bs[ob][0][bn * ASTRIDE + bkh]) = pba;
            *reinterpret_cast<uint4*>(&Bs[ob][1][bn * ASTRIDE + bkh]) = pbb;
        }
        __syncthreads();
        buf ^= 1;
    }

    // ---- epilogue: + b1, LIF with margin tracking, write spikes ----
    float cur[2][4][4];
    #pragma unroll
    for (int nt = 0; nt < 4; nt++) {
        float2 bv = *reinterpret_cast<const float2*>(&b1[wn * 32 + nt * 8 + tg * 2]);
        #pragma unroll
        for (int mt = 0; mt < 2; mt++) {
            cur[mt][nt][0] = acc[mt][nt][0] + bv.x;
            cur[mt][nt][1] = acc[mt][nt][1] + bv.y;
            cur[mt][nt][2] = acc[mt][nt][2] + bv.x;
            cur[mt][nt][3] = acc[mt][nt][3] + bv.y;
        }
    }

    float mem[2][4][4];
    unsigned badm[2][4];
    #pragma unroll
    for (int mt = 0; mt < 2; mt++)
        #pragma unroll
        for (int nt = 0; nt < 4; nt++) {
            badm[mt][nt] = 0u;
            #pragma unroll
            for (int r = 0; r < 4; r++) mem[mt][nt][r] = 0.0f;
        }

    for (int t = 0; t < TSTEPS; t++) {
        float* pt = out_spk + (size_t)t * ((size_t)BATCH * HID);
        #pragma unroll
        for (int mt = 0; mt < 2; mt++) {
            int r0 = m0 + wm * 32 + mt * 16 + g;
            #pragma unroll
            for (int nt = 0; nt < 4; nt++) {
                int n = wn * 32 + nt * 8 + tg * 2;
                float s[4];
                #pragma unroll
                for (int r = 0; r < 4; r++) {
                    float m = fmaf(mem[mt][nt][r], DECAYF, cur[mt][nt][r]);
                    if (fabsf(m - THRESHF) < EPSM) badm[mt][nt] |= (1u << r);
                    s[r] = (m > THRESHF) ? 1.0f : 0.0f;
                    mem[mt][nt][r] = (s[r] != 0.0f) ? 0.0f : m;
                }
                float2 v0 = {s[0], s[1]};
                float2 v1 = {s[2], s[3]};
                *reinterpret_cast<float2*>(&pt[(size_t)r0 * HID + n])       = v0;
                *reinterpret_cast<float2*>(&pt[(size_t)(r0 + 8) * HID + n]) = v1;
            }
        }
    }

    #pragma unroll
    for (int mt = 0; mt < 2; mt++)
        #pragma unroll
        for (int nt = 0; nt < 4; nt++)
            if (badm[mt][nt]) {
                #pragma unroll
                for (int r = 0; r < 4; r++)
                    if (badm[mt][nt] & (1u << r)) {
                        int row = m0 + wm * 32 + mt * 16 + g + ((r >> 1) ? 8 : 0);
                        int col = wn * 32 + nt * 8 + tg * 2 + (r & 1);
                        unsigned pos = atomicAdd(&g_fix_cnt, 1u);
                        if (pos < FIXCAP)
                            g_fix_list[pos] = (unsigned)(row * HID + col);
                    }
            }
}

// ---------------------------------------------------------------------------
// K1b fixup: exact sequential-k fp32 recompute (bitwise R1 recipe).
// R12: one thread per entry (262K threads), unrolled load stream. The fmaf
// chain stays strictly sequential ascending-k -> bitwise identical results;
// unrolling only batches the loads ahead of the dependent chain.
// ---------------------------------------------------------------------------
__global__ __launch_bounds__(256) void k1_fixup(
    const float* __restrict__ x, const float* __restrict__ W1,
    const float* __restrict__ b1, float* __restrict__ out_spk)
{
    const unsigned cnt = min(*(volatile unsigned*)&g_fix_cnt, (unsigned)FIXCAP);
    const unsigned stride = gridDim.x * blockDim.x;

    for (unsigned i = blockIdx.x * blockDim.x + threadIdx.x; i < cnt; i += stride) {
        unsigned idx = g_fix_list[i];
        int b = idx >> 7;
        int j = idx & (HID - 1);

        const float* xr = x  + (size_t)b * INF;
        const float* wr = W1 + (size_t)j * INF;
        float a = 0.0f;
        #pragma unroll 8
        for (int k = 0; k < INF; k++)
            a = fmaf(__ldg(&xr[k]), __ldg(&wr[k]), a);
        float curv = a + __ldg(&b1[j]);

        float m = 0.0f;
        #pragma unroll
        for (int t = 0; t < TSTEPS; t++) {
            m = fmaf(m, DECAYF, curv);
            float s = (m > THRESHF) ? 1.0f : 0.0f;
            out_spk[(size_t)t * ((size_t)BATCH * HID) + idx] = s;
            m = (s != 0.0f) ? 0.0f : m;
        }
    }
}

// ---------------------------------------------------------------------------
// K3: c2 = spk @ W2^T (verbatim R5 — proven, bitwise == R1 chain).
// ---------------------------------------------------------------------------
__global__ __launch_bounds__(256) void k3_gemm2(
    const float* __restrict__ spk, const float* __restrict__ W2)
{
    __shared__ float sh[256][33];
    __shared__ float W2t[HID][12];

    const int tid = threadIdx.x;
    for (int i = tid; i < HID * NCLS; i += 256) {
        int j = i / NCLS;
        int o = i - j * NCLS;
        W2t[j][o] = W2[o * HID + j];
    }

    const size_t row0 = (size_t)blockIdx.x * 256;
    float acc[NCLS];
    #pragma unroll
    for (int o = 0; o < NCLS; o++) acc[o] = 0.0f;

    for (int jc = 0; jc < 4; jc++) {
        __syncthreads();
        #pragma unroll
        for (int s4 = 0; s4 < 8; s4++) {
            int f = tid + s4 * 256;
            int r = f >> 3;
            int q = f & 7;
            float4 v = *reinterpret_cast<const float4*>(
                &spk[(row0 + r) * HID + jc * 32 + q * 4]);
            sh[r][q * 4 + 0] = v.x; sh[r][q * 4 + 1] = v.y;
            sh[r][q * 4 + 2] = v.z; sh[r][q * 4 + 3] = v.w;
        }
        __syncthreads();
        #pragma unroll
        for (int j = 0; j < 32; j++) {
            float s = sh[tid][j];
            const float* wr = W2t[jc * 32 + j];
            float4 w0 = *reinterpret_cast<const float4*>(wr);
            float4 w1 = *reinterpret_cast<const float4*>(wr + 4);
            float2 w2 = *reinterpret_cast<const float2*>(wr + 8);
            acc[0] = fmaf(s, w0.x, acc[0]);
            acc[1] = fmaf(s, w0.y, acc[1]);
            acc[2] = fmaf(s, w0.z, acc[2]);
            acc[3] = fmaf(s, w0.w, acc[3]);
            acc[4] = fmaf(s, w1.x, acc[4]);
            acc[5] = fmaf(s, w1.y, acc[5]);
            acc[6] = fmaf(s, w1.z, acc[6]);
            acc[7] = fmaf(s, w1.w, acc[7]);
            acc[8] = fmaf(s, w2.x, acc[8]);
            acc[9] = fmaf(s, w2.y, acc[9]);
        }
    }

    const size_t r = row0 + tid;
    #pragma unroll
    for (int o = 0; o < NCLS; o++)
        g_c2[r * NCLS + o] = acc[o];
}

// ---------------------------------------------------------------------------
__global__ __launch_bounds__(256) void k4_lif2(
    const float* __restrict__ b2, float* __restrict__ outp)
{
    const int id = blockIdx.x * blockDim.x + threadIdx.x;
    const int o = id % NCLS;
    const float bias = __ldg(&b2[o]);

    float mem = 0.0f, acc = 0.0f;
    #pragma unroll
    for (int t = 0; t < TSTEPS; t++) {
        float v = fmaf(mem, DECAYF, g_c2[(size_t)t * (BATCH * NCLS) + id]);
        v = v + bias;
        float s = (v > THRESHF) ? 1.0f : 0.0f;
        acc += s;
        mem = (s != 0.0f) ? 0.0f : v;
    }
    outp[id] = acc;
}

// ---------------------------------------------------------------------------
extern "C" void kernel_launch(void* const* d_in, const int* in_sizes, int n_in,
                              void* d_out, int out_size)
{
    const float* x  = (const float*)d_in[0];
    const float* W1 = (const float*)d_in[1];
    const float* b1 = (const float*)d_in[2];
    const float* W2 = (const float*)d_in[3];
    const float* b2 = (const float*)d_in[4];
    float* out = (float*)d_out;

    float* out_output = out;
    float* out_spk    = out + (size_t)BATCH * NCLS;

    k0_init<<<(HID * INF + 255) / 256, 256>>>(W1);
    k1_mma<<<BATCH / 64, 256>>>(x, b1, out_spk);
    k1_fixup<<<1024, 256>>>(x, W1, b1, out_spk);
    k3_gemm2<<<(TSTEPS * BATCH) / 256, 256>>>(out_spk, W2);
    k4_lif2<<<(BATCH * NCLS) / 256, 256>>>(b2, out_output);
}

// round 13
// speedup vs baseline: 1.4669x; 1.0978x over previous
#include <cuda_runtime.h>
#include <cuda_bf16.h>

#define BATCH   32768
#define HID     128
#define INF     784
#define NCLS    10
#define TSTEPS  20

#define DECAYF  0.25f
#define THRESHF 1.0f
#define EPSM    2e-4f

#define KCHUNKS (INF / 16)      // 49
#define FIXCAP  (1 << 21)

// Scratch (device globals)
__device__ float    g_c2[(size_t)TSTEPS * BATCH * NCLS];
__device__ unsigned g_fix_list[FIXCAP];
__device__ unsigned g_fix_cnt;
__device__ __align__(16) unsigned g_bits[(size_t)TSTEPS * BATCH * 4];  // 10.5MB
__device__ __align__(16) unsigned short g_w1a[HID * INF];   // bf16 hi plane
__device__ __align__(16) unsigned short g_w1b[HID * INF];   // bf16 lo plane

// ---------------------------------------------------------------------------
__device__ __forceinline__ void split2(float v, unsigned short& h0, unsigned short& h1)
{
    __nv_bfloat16 b0 = __float2bfloat16_rn(v);
    float r = v - __bfloat162float(b0);
    __nv_bfloat16 b1 = __float2bfloat16_rn(r);
    h0 = __bfloat16_as_ushort(b0);
    h1 = __bfloat16_as_ushort(b1);
}

__device__ __forceinline__ void mma_bf16(float* d, const unsigned* a, const unsigned* b)
{
    asm volatile(
        "mma.sync.aligned.m16n8k16.row.col.f32.bf16.bf16.f32 "
        "{%0,%1,%2,%3}, {%4,%5,%6,%7}, {%8,%9}, {%0,%1,%2,%3};"
        : "+f"(d[0]), "+f"(d[1]), "+f"(d[2]), "+f"(d[3])
        : "r"(a[0]), "r"(a[1]), "r"(a[2]), "r"(a[3]), "r"(b[0]), "r"(b[1]));
}

__global__ void k0_init(const float* __restrict__ W1)
{
    if (blockIdx.x == 0 && threadIdx.x == 0) g_fix_cnt = 0;
    int i = blockIdx.x * blockDim.x + threadIdx.x;
    if (i < HID * INF) {
        unsigned short h0, h1;
        split2(W1[i], h0, h1);
        g_w1a[i] = h0;
        g_w1b[i] = h1;
    }
}

// ---------------------------------------------------------------------------
// K1: R5 tensor GEMM1 + LIF + margin tracking + bitpacked spike emission.
// Tile M=64 x N=128, 256 threads = 8 warps (2m x 4n).
// ---------------------------------------------------------------------------
#define ASTRIDE 24

__global__ __launch_bounds__(256) void k1_mma(
    const float* __restrict__ x, const float* __restrict__ b1,
    float* __restrict__ out_spk)
{
    __shared__ unsigned short As[2][2][64  * ASTRIDE];
    __shared__ unsigned short Bs[2][2][128 * ASTRIDE];

    const int tid  = threadIdx.x;
    const int lane = tid & 31;
    const int wid  = tid >> 5;
    const int g    = lane >> 2;
    const int tg   = lane & 3;
    const int wm   = wid >> 2;
    const int wn   = wid & 3;
    const int m0   = blockIdx.x * 64;

    const int sm  = tid >> 2;
    const int skq = (tid & 3) * 4;
    const int bn  = tid >> 1;
    const int bkh = (tid & 1) * 8;

    float acc[2][4][4];
    #pragma unroll
    for (int mt = 0; mt < 2; mt++)
        #pragma unroll
        for (int nt = 0; nt < 4; nt++)
            #pragma unroll
            for (int r = 0; r < 4; r++) acc[mt][nt][r] = 0.0f;

    // ---- prologue: stage chunk 0 into buf 0 ----
    {
        float4 ax = *reinterpret_cast<const float4*>(&x[(size_t)(m0 + sm) * INF + skq]);
        float av[4] = {ax.x, ax.y, ax.z, ax.w};
        unsigned short p0[4], p1[4];
        #pragma unroll
        for (int i = 0; i < 4; i++) split2(av[i], p0[i], p1[i]);
        *reinterpret_cast<uint2*>(&As[0][0][sm * ASTRIDE + skq]) = *reinterpret_cast<uint2*>(p0);
        *reinterpret_cast<uint2*>(&As[0][1][sm * ASTRIDE + skq]) = *reinterpret_cast<uint2*>(p1);

        uint4 va = *reinterpret_cast<const uint4*>(&g_w1a[bn * INF + bkh]);
        uint4 vb = *reinterpret_cast<const uint4*>(&g_w1b[bn * INF + bkh]);
        *reinterpret_cast<uint4*>(&Bs[0][0][bn * ASTRIDE + bkh]) = va;
        *reinterpret_cast<uint4*>(&Bs[0][1][bn * ASTRIDE + bkh]) = vb;
    }
    __syncthreads();

    int buf = 0;
    for (int kc = 0; kc < KCHUNKS; kc++) {
        float4 pax;
        uint4 pba, pbb;
        if (kc < KCHUNKS - 1) {
            int k0 = (kc + 1) * 16;
            pax = *reinterpret_cast<const float4*>(&x[(size_t)(m0 + sm) * INF + k0 + skq]);
            pba = *reinterpret_cast<const uint4*>(&g_w1a[bn * INF + k0 + bkh]);
            pbb = *reinterpret_cast<const uint4*>(&g_w1b[bn * INF + k0 + bkh]);
        }

        unsigned aF[2][2][4];
        #pragma unroll
        for (int s = 0; s < 2; s++)
            #pragma unroll
            for (int mt = 0; mt < 2; mt++) {
                const unsigned short* ab = &As[buf][s][(wm * 32 + mt * 16) * ASTRIDE];
                aF[s][mt][0] = *reinterpret_cast<const unsigned*>(&ab[(g)     * ASTRIDE + tg * 2]);
                aF[s][mt][1] = *reinterpret_cast<const unsigned*>(&ab[(g + 8) * ASTRIDE + tg * 2]);
                aF[s][mt][2] = *reinterpret_cast<const unsigned*>(&ab[(g)     * ASTRIDE + tg * 2 + 8]);
                aF[s][mt][3] = *reinterpret_cast<const unsigned*>(&ab[(g + 8) * ASTRIDE + tg * 2 + 8]);
            }
        unsigned bF[2][4][2];
        #pragma unroll
        for (int s = 0; s < 2; s++)
            #pragma unroll
            for (int nt = 0; nt < 4; nt++) {
                const unsigned short* bb = &Bs[buf][s][(wn * 32 + nt * 8 + g) * ASTRIDE];
                bF[s][nt][0] = *reinterpret_cast<const unsigned*>(&bb[tg * 2]);
                bF[s][nt][1] = *reinterpret_cast<const unsigned*>(&bb[tg * 2 + 8]);
            }

        #pragma unroll
        for (int p = 0; p < 3; p++) {
            const int PI[3] = {0, 0, 1};
            const int PJ[3] = {0, 1, 0};
            int i = PI[p], j = PJ[p];
            #pragma unroll
            for (int mt = 0; mt < 2; mt++)
                #pragma unroll
                for (int nt = 0; nt < 4; nt++)
                    mma_bf16(acc[mt][nt], aF[i][mt], bF[j][nt]);
        }

        if (kc < KCHUNKS - 1) {
            int ob = buf ^ 1;
            float av[4] = {pax.x, pax.y, pax.z, pax.w};
            unsigned short p0[4], p1[4];
            #pragma unroll
            for (int i = 0; i < 4; i++) split2(av[i], p0[i], p1[i]);
            *reinterpret_cast<uint2*>(&As[ob][0][sm * ASTRIDE + skq]) = *reinterpret_cast<uint2*>(p0);
            *reinterpret_cast<uint2*>(&As[ob][1][sm * ASTRIDE + skq]) = *reinterpret_cast<uint2*>(p1);
            *reinterpret_cast<uint4*>(&Bs[ob][0][bn * ASTRIDE + bkh]) = pba;
            *reinterpret_cast<uint4*>(&Bs[ob][1][bn * ASTRIDE + bkh]) = pbb;
        }
        __syncthreads();
        buf ^= 1;
    }

    // ---- epilogue: + b1, LIF with margin tracking, float + bitpack stores ----
    float cur[2][4][4];
    #pragma unroll
    for (int nt = 0; nt < 4; nt++) {
        float2 bv = *reinterpret_cast<const float2*>(&b1[wn * 32 + nt * 8 + tg * 2]);
        #pragma unroll
        for (int mt = 0; mt < 2; mt++) {
            cur[mt][nt][0] = acc[mt][nt][0] + bv.x;
            cur[mt][nt][1] = acc[mt][nt][1] + bv.y;
            cur[mt][nt][2] = acc[mt][nt][2] + bv.x;
            cur[mt][nt][3] = acc[mt][nt][3] + bv.y;
        }
    }

    float mem[2][4][4];
    unsigned badm[2][4];
    #pragma unroll
    for (int mt = 0; mt < 2; mt++)
        #pragma unroll
        for (int nt = 0; nt < 4; nt++) {
            badm[mt][nt] = 0u;
            #pragma unroll
            for (int r = 0; r < 4; r++) mem[mt][nt][r] = 0.0f;
        }

    for (int t = 0; t < TSTEPS; t++) {
        float* pt = out_spk + (size_t)t * ((size_t)BATCH * HID);
        #pragma unroll
        for (int mt = 0; mt < 2; mt++) {
            int r0 = m0 + wm * 32 + mt * 16 + g;
            unsigned mA = 0u, mB = 0u;
            #pragma unroll
            for (int nt = 0; nt < 4; nt++) {
                int n = wn * 32 + nt * 8 + tg * 2;
                float s[4];
                #pragma unroll
                for (int r = 0; r < 4; r++) {
                    float m = fmaf(mem[mt][nt][r], DECAYF, cur[mt][nt][r]);
                    if (fabsf(m - THRESHF) < EPSM) badm[mt][nt] |= (1u << r);
                    s[r] = (m > THRESHF) ? 1.0f : 0.0f;
                    mem[mt][nt][r] = (s[r] != 0.0f) ? 0.0f : m;
                }
                float2 v0 = {s[0], s[1]};
                float2 v1 = {s[2], s[3]};
                *reinterpret_cast<float2*>(&pt[(size_t)r0 * HID + n])       = v0;
                *reinterpret_cast<float2*>(&pt[(size_t)(r0 + 8) * HID + n]) = v1;
                unsigned sh = nt * 8 + tg * 2;
                mA |= (((s[0] != 0.0f) ? 1u : 0u) | ((s[1] != 0.0f) ? 2u : 0u)) << sh;
                mB |= (((s[2] != 0.0f) ? 1u : 0u) | ((s[3] != 0.0f) ? 2u : 0u)) << sh;
            }
            // OR-combine across the 4 tg lanes (same g; lanes differ in bits 0-1)
            mA |= __shfl_xor_sync(0xffffffffu, mA, 1);
            mA |= __shfl_xor_sync(0xffffffffu, mA, 2);
            mB |= __shfl_xor_sync(0xffffffffu, mB, 1);
            mB |= __shfl_xor_sync(0xffffffffu, mB, 2);
            if (tg == 0) {
                g_bits[((size_t)t * BATCH + r0) * 4 + wn]     = mA;
                g_bits[((size_t)t * BATCH + r0 + 8) * 4 + wn] = mB;
            }
        }
    }

    #pragma unroll
    for (int mt = 0; mt < 2; mt++)
        #pragma unroll
        for (int nt = 0; nt < 4; nt++)
            if (badm[mt][nt]) {
                #pragma unroll
                for (int r = 0; r < 4; r++)
                    if (badm[mt][nt] & (1u << r)) {
                        int row = m0 + wm * 32 + mt * 16 + g + ((r >> 1) ? 8 : 0);
                        int col = wn * 32 + nt * 8 + tg * 2 + (r & 1);
                        unsigned pos = atomicAdd(&g_fix_cnt, 1u);
                        if (pos < FIXCAP)
                            g_fix_list[pos] = (unsigned)(row * HID + col);
                    }
            }
}

// ---------------------------------------------------------------------------
// K1b fixup: exact sequential-k fp32 recompute (bitwise R1 recipe), with
// unrolled load stream (chain order unchanged) + bitpack patch.
// ---------------------------------------------------------------------------
__global__ __launch_bounds__(256) void k1_fixup(
    const float* __restrict__ x, const float* __restrict__ W1,
    const float* __restrict__ b1, float* __restrict__ out_spk)
{
    const unsigned cnt = min(*(volatile unsigned*)&g_fix_cnt, (unsigned)FIXCAP);
    const unsigned stride = gridDim.x * blockDim.x;

    for (unsigned i = blockIdx.x * blockDim.x + threadIdx.x; i < cnt; i += stride) {
        unsigned idx = g_fix_list[i];
        int b = idx >> 7;
        int j = idx & (HID - 1);

        const float* xr = x  + (size_t)b * INF;
        const float* wr = W1 + (size_t)j * INF;
        float a = 0.0f;
        #pragma unroll 8
        for (int k = 0; k < INF; k++)
            a = fmaf(__ldg(&xr[k]), __ldg(&wr[k]), a);
        float curv = a + __ldg(&b1[j]);

        const int wordi = j >> 5;
        const unsigned bit = 1u << (j & 31);

        float m = 0.0f;
        #pragma unroll
        for (int t = 0; t < TSTEPS; t++) {
            m = fmaf(m, DECAYF, curv);
            float s = (m > THRESHF) ? 1.0f : 0.0f;
            out_spk[(size_t)t * ((size_t)BATCH * HID) + idx] = s;
            unsigned* bp = &g_bits[((size_t)t * BATCH + b) * 4 + wordi];
            if (s != 0.0f) atomicOr(bp, bit);
            else           atomicAnd(bp, ~bit);
            m = (s != 0.0f) ? 0.0f : m;
        }
    }
}

// ---------------------------------------------------------------------------
// K3: c2 from bitpacked spikes, spikes reconstructed in registers.
// Same ascending-j fmaf chain as the proven R5 k3 -> bitwise identical c2.
// One thread per (t,b) row; reads 16B of bits instead of 512B of floats.
// ---------------------------------------------------------------------------
__global__ __launch_bounds__(256) void k3_bits(const float* __restrict__ W2)
{
    __shared__ float W2t[HID][12];
    const int tid = threadIdx.x;
    for (int i = tid; i < HID * NCLS; i += 256) {
        int j = i / NCLS;
        int o = i - j * NCLS;
        W2t[j][o] = W2[o * HID + j];
    }
    __syncthreads();

    const size_t row = (size_t)blockIdx.x * 256 + tid;   // over TSTEPS*BATCH
    uint4 bw = *reinterpret_cast<const uint4*>(&g_bits[row * 4]);
    unsigned wds[4] = {bw.x, bw.y, bw.z, bw.w};

    float acc[NCLS];
    #pragma unroll
    for (int o = 0; o < NCLS; o++) acc[o] = 0.0f;

    for (int w = 0; w < 4; w++) {
        unsigned word = wds[w];
        #pragma unroll
        for (int b = 0; b < 32; b++) {
            float s = ((word >> b) & 1u) ? 1.0f : 0.0f;
            const float* wr = W2t[w * 32 + b];
            float4 w0 = *reinterpret_cast<const float4*>(wr);
            float4 w1 = *reinterpret_cast<const float4*>(wr + 4);
            float2 w2 = *reinterpret_cast<const float2*>(wr + 8);
            acc[0] = fmaf(s, w0.x, acc[0]);
            acc[1] = fmaf(s, w0.y, acc[1]);
            acc[2] = fmaf(s, w0.z, acc[2]);
            acc[3] = fmaf(s, w0.w, acc[3]);
            acc[4] = fmaf(s, w1.x, acc[4]);
            acc[5] = fmaf(s, w1.y, acc[5]);
            acc[6] = fmaf(s, w1.z, acc[6]);
            acc[7] = fmaf(s, w1.w, acc[7]);
            acc[8] = fmaf(s, w2.x, acc[8]);
            acc[9] = fmaf(s, w2.y, acc[9]);
        }
    }

    float* cp = &g_c2[row * NCLS];
    #pragma unroll
    for (int o = 0; o < NCLS; o++) cp[o] = acc[o];
}

// ---------------------------------------------------------------------------
__global__ __launch_bounds__(256) void k4_lif2(
    const float* __restrict__ b2, float* __restrict__ outp)
{
    const int id = blockIdx.x * blockDim.x + threadIdx.x;
    const int o = id % NCLS;
    const float bias = __ldg(&b2[o]);

    float mem = 0.0f, acc = 0.0f;
    #pragma unroll
    for (int t = 0; t < TSTEPS; t++) {
        float v = fmaf(mem, DECAYF, g_c2[(size_t)t * (BATCH * NCLS) + id]);
        v = v + bias;
        float s = (v > THRESHF) ? 1.0f : 0.0f;
        acc += s;
        mem = (s != 0.0f) ? 0.0f : v;
    }
    outp[id] = acc;
}

// ---------------------------------------------------------------------------
extern "C" void kernel_launch(void* const* d_in, const int* in_sizes, int n_in,
                              void* d_out, int out_size)
{
    const float* x  = (const float*)d_in[0];
    const float* W1 = (const float*)d_in[1];
    const float* b1 = (const float*)d_in[2];
    const float* W2 = (const float*)d_in[3];
    const float* b2 = (const float*)d_in[4];
    float* out = (float*)d_out;

    float* out_output = out;
    float* out_spk    = out + (size_t)BATCH * NCLS;

    k0_init<<<(HID * INF + 255) / 256, 256>>>(W1);
    k1_mma<<<BATCH / 64, 256>>>(x, b1, out_spk);
    k1_fixup<<<1024, 256>>>(x, W1, b1, out_spk);
    k3_bits<<<(TSTEPS * BATCH) / 256, 256>>>(W2);
    k4_lif2<<<(BATCH * NCLS) / 256, 256>>>(b2, out_output);
}

// round 14
// speedup vs baseline: 1.7481x; 1.1917x over previous
#include <cuda_runtime.h>
#include <cuda_bf16.h>

#define BATCH   32768
#define HID     128
#define INF     784
#define NCLS    10
#define TSTEPS  20

#define DECAYF  0.25f
#define THRESHF 1.0f
#define EPSM    2e-4f

#define KCHUNKS (INF / 16)      // 49
#define FIXCAP  (1 << 21)

// Scratch (device globals)
__device__ float    g_c2[(size_t)TSTEPS * BATCH * NCLS];
__device__ unsigned g_fix_list[FIXCAP];
__device__ unsigned g_fix_cnt;
__device__ __align__(16) unsigned g_bits[(size_t)TSTEPS * BATCH * 4];  // 10.5MB
__device__ __align__(16) unsigned short g_w1a[HID * INF];   // bf16 hi plane
__device__ __align__(16) unsigned short g_w1b[HID * INF];   // bf16 lo plane

// Bit layout inside word w (cols w*32..w*32+31):  col = w*32 + nt*8 + tg*2 + b
//   bit position = tg*8 + nt*2 + b     (thread (tg) owns contiguous byte tg)

// ---------------------------------------------------------------------------
__device__ __forceinline__ void split2(float v, unsigned short& h0, unsigned short& h1)
{
    __nv_bfloat16 b0 = __float2bfloat16_rn(v);
    float r = v - __bfloat162float(b0);
    __nv_bfloat16 b1 = __float2bfloat16_rn(r);
    h0 = __bfloat16_as_ushort(b0);
    h1 = __bfloat16_as_ushort(b1);
}

__device__ __forceinline__ void mma_bf16(float* d, const unsigned* a, const unsigned* b)
{
    asm volatile(
        "mma.sync.aligned.m16n8k16.row.col.f32.bf16.bf16.f32 "
        "{%0,%1,%2,%3}, {%4,%5,%6,%7}, {%8,%9}, {%0,%1,%2,%3};"
        : "+f"(d[0]), "+f"(d[1]), "+f"(d[2]), "+f"(d[3])
        : "r"(a[0]), "r"(a[1]), "r"(a[2]), "r"(a[3]), "r"(b[0]), "r"(b[1]));
}

__global__ void k0_init(const float* __restrict__ W1)
{
    if (blockIdx.x == 0 && threadIdx.x == 0) g_fix_cnt = 0;
    int i = blockIdx.x * blockDim.x + threadIdx.x;
    if (i < HID * INF) {
        unsigned short h0, h1;
        split2(W1[i], h0, h1);
        g_w1a[i] = h0;
        g_w1b[i] = h1;
    }
}

// ---------------------------------------------------------------------------
// K1: R5 tensor GEMM1 + LIF + margin tracking + shfl-free byte bit emission.
// Tile M=64 x N=128, 256 threads = 8 warps (2m x 4n).
// ---------------------------------------------------------------------------
#define ASTRIDE 24

__global__ __launch_bounds__(256) void k1_mma(
    const float* __restrict__ x, const float* __restrict__ b1,
    float* __restrict__ out_spk)
{
    __shared__ unsigned short As[2][2][64  * ASTRIDE];
    __shared__ unsigned short Bs[2][2][128 * ASTRIDE];

    const int tid  = threadIdx.x;
    const int lane = tid & 31;
    const int wid  = tid >> 5;
    const int g    = lane >> 2;
    const int tg   = lane & 3;
    const int wm   = wid >> 2;
    const int wn   = wid & 3;
    const int m0   = blockIdx.x * 64;

    const int sm  = tid >> 2;
    const int skq = (tid & 3) * 4;
    const int bn  = tid >> 1;
    const int bkh = (tid & 1) * 8;

    float acc[2][4][4];
    #pragma unroll
    for (int mt = 0; mt < 2; mt++)
        #pragma unroll
        for (int nt = 0; nt < 4; nt++)
            #pragma unroll
            for (int r = 0; r < 4; r++) acc[mt][nt][r] = 0.0f;

    // ---- prologue: stage chunk 0 into buf 0 ----
    {
        float4 ax = *reinterpret_cast<const float4*>(&x[(size_t)(m0 + sm) * INF + skq]);
        float av[4] = {ax.x, ax.y, ax.z, ax.w};
        unsigned short p0[4], p1[4];
        #pragma unroll
        for (int i = 0; i < 4; i++) split2(av[i], p0[i], p1[i]);
        *reinterpret_cast<uint2*>(&As[0][0][sm * ASTRIDE + skq]) = *reinterpret_cast<uint2*>(p0);
        *reinterpret_cast<uint2*>(&As[0][1][sm * ASTRIDE + skq]) = *reinterpret_cast<uint2*>(p1);

        uint4 va = *reinterpret_cast<const uint4*>(&g_w1a[bn * INF + bkh]);
        uint4 vb = *reinterpret_cast<const uint4*>(&g_w1b[bn * INF + bkh]);
        *reinterpret_cast<uint4*>(&Bs[0][0][bn * ASTRIDE + bkh]) = va;
        *reinterpret_cast<uint4*>(&Bs[0][1][bn * ASTRIDE + bkh]) = vb;
    }
    __syncthreads();

    int buf = 0;
    for (int kc = 0; kc < KCHUNKS; kc++) {
        float4 pax;
        uint4 pba, pbb;
        if (kc < KCHUNKS - 1) {
            int k0 = (kc + 1) * 16;
            pax = *reinterpret_cast<const float4*>(&x[(size_t)(m0 + sm) * INF + k0 + skq]);
            pba = *reinterpret_cast<const uint4*>(&g_w1a[bn * INF + k0 + bkh]);
            pbb = *reinterpret_cast<const uint4*>(&g_w1b[bn * INF + k0 + bkh]);
        }

        unsigned aF[2][2][4];
        #pragma unroll
        for (int s = 0; s < 2; s++)
            #pragma unroll
            for (int mt = 0; mt < 2; mt++) {
                const unsigned short* ab = &As[buf][s][(wm * 32 + mt * 16) * ASTRIDE];
                aF[s][mt][0] = *reinterpret_cast<const unsigned*>(&ab[(g)     * ASTRIDE + tg * 2]);
                aF[s][mt][1] = *reinterpret_cast<const unsigned*>(&ab[(g + 8) * ASTRIDE + tg * 2]);
                aF[s][mt][2] = *reinterpret_cast<const unsigned*>(&ab[(g)     * ASTRIDE + tg * 2 + 8]);
                aF[s][mt][3] = *reinterpret_cast<const unsigned*>(&ab[(g + 8) * ASTRIDE + tg * 2 + 8]);
            }
        unsigned bF[2][4][2];
        #pragma unroll
        for (int s = 0; s < 2; s++)
            #pragma unroll
            for (int nt = 0; nt < 4; nt++) {
                const unsigned short* bb = &Bs[buf][s][(wn * 32 + nt * 8 + g) * ASTRIDE];
                bF[s][nt][0] = *reinterpret_cast<const unsigned*>(&bb[tg * 2]);
                bF[s][nt][1] = *reinterpret_cast<const unsigned*>(&bb[tg * 2 + 8]);
            }

        #pragma unroll
        for (int p = 0; p < 3; p++) {
            const int PI[3] = {0, 0, 1};
            const int PJ[3] = {0, 1, 0};
            int i = PI[p], j = PJ[p];
            #pragma unroll
            for (int mt = 0; mt < 2; mt++)
                #pragma unroll
                for (int nt = 0; nt < 4; nt++)
                    mma_bf16(acc[mt][nt], aF[i][mt], bF[j][nt]);
        }

        if (kc < KCHUNKS - 1) {
            int ob = buf ^ 1;
            float av[4] = {pax.x, pax.y, pax.z, pax.w};
            unsigned short p0[4], p1[4];
            #pragma unroll
            for (int i = 0; i < 4; i++) split2(av[i], p0[i], p1[i]);
            *reinterpret_cast<uint2*>(&As[ob][0][sm * ASTRIDE + skq]) = *reinterpret_cast<uint2*>(p0);
            *reinterpret_cast<uint2*>(&As[ob][1][sm * ASTRIDE + skq]) = *reinterpret_cast<uint2*>(p1);
            *reinterpret_cast<uint4*>(&Bs[ob][0][bn * ASTRIDE + bkh]) = pba;
            *reinterpret_cast<uint4*>(&Bs[ob][1][bn * ASTRIDE + bkh]) = pbb;
        }
        __syncthreads();
        buf ^= 1;
    }

    // ---- epilogue: + b1, LIF with margin tracking, float + byte-bit stores ----
    float cur[2][4][4];
    #pragma unroll
    for (int nt = 0; nt < 4; nt++) {
        float2 bv = *reinterpret_cast<const float2*>(&b1[wn * 32 + nt * 8 + tg * 2]);
        #pragma unroll
        for (int mt = 0; mt < 2; mt++) {
            cur[mt][nt][0] = acc[mt][nt][0] + bv.x;
            cur[mt][nt][1] = acc[mt][nt][1] + bv.y;
            cur[mt][nt][2] = acc[mt][nt][2] + bv.x;
            cur[mt][nt][3] = acc[mt][nt][3] + bv.y;
        }
    }

    float mem[2][4][4];
    unsigned badm[2][4];
    #pragma unroll
    for (int mt = 0; mt < 2; mt++)
        #pragma unroll
        for (int nt = 0; nt < 4; nt++) {
            badm[mt][nt] = 0u;
            #pragma unroll
            for (int r = 0; r < 4; r++) mem[mt][nt][r] = 0.0f;
        }

    unsigned char* bbytes = (unsigned char*)g_bits;
    const int bytecol = wn * 4 + tg;     // byte index within the 16B row record

    for (int t = 0; t < TSTEPS; t++) {
        float* pt = out_spk + (size_t)t * ((size_t)BATCH * HID);
        #pragma unroll
        for (int mt = 0; mt < 2; mt++) {
            int r0 = m0 + wm * 32 + mt * 16 + g;
            unsigned byteA = 0u, byteB = 0u;
            #pragma unroll
            for (int nt = 0; nt < 4; nt++) {
                int n = wn * 32 + nt * 8 + tg * 2;
                float s[4];
                #pragma unroll
                for (int r = 0; r < 4; r++) {
                    float m = fmaf(mem[mt][nt][r], DECAYF, cur[mt][nt][r]);
                    if (fabsf(m - THRESHF) < EPSM) badm[mt][nt] |= (1u << r);
                    s[r] = (m > THRESHF) ? 1.0f : 0.0f;
                    mem[mt][nt][r] = (s[r] != 0.0f) ? 0.0f : m;
                }
                float2 v0 = {s[0], s[1]};
                float2 v1 = {s[2], s[3]};
                *reinterpret_cast<float2*>(&pt[(size_t)r0 * HID + n])       = v0;
                *reinterpret_cast<float2*>(&pt[(size_t)(r0 + 8) * HID + n]) = v1;
                byteA |= (((s[0] != 0.0f) ? 1u : 0u) | ((s[1] != 0.0f) ? 2u : 0u)) << (nt * 2);
                byteB |= (((s[2] != 0.0f) ? 1u : 0u) | ((s[3] != 0.0f) ? 2u : 0u)) << (nt * 2);
            }
            bbytes[((size_t)t * BATCH + r0) * 16 + bytecol]       = (unsigned char)byteA;
            bbytes[((size_t)t * BATCH + r0 + 8) * 16 + bytecol]   = (unsigned char)byteB;
        }
    }

    #pragma unroll
    for (int mt = 0; mt < 2; mt++)
        #pragma unroll
        for (int nt = 0; nt < 4; nt++)
            if (badm[mt][nt]) {
                #pragma unroll
                for (int r = 0; r < 4; r++)
                    if (badm[mt][nt] & (1u << r)) {
                        int row = m0 + wm * 32 + mt * 16 + g + ((r >> 1) ? 8 : 0);
                        int col = wn * 32 + nt * 8 + tg * 2 + (r & 1);
                        unsigned pos = atomicAdd(&g_fix_cnt, 1u);
                        if (pos < FIXCAP)
                            g_fix_list[pos] = (unsigned)(row * HID + col);
                    }
            }
}

// ---------------------------------------------------------------------------
// K1b fixup: exact sequential-k fp32 recompute (bitwise R1 recipe, R5 config)
// + permuted-bit patch via word atomics.
// ---------------------------------------------------------------------------
__global__ __launch_bounds__(128) void k1_fixup(
    const float* __restrict__ x, const float* __restrict__ W1,
    const float* __restrict__ b1, float* __restrict__ out_spk)
{
    const unsigned cnt = min(*(volatile unsigned*)&g_fix_cnt, (unsigned)FIXCAP);
    const int stride = gridDim.x * blockDim.x;

    for (unsigned i = blockIdx.x * blockDim.x + threadIdx.x; i < cnt; i += stride) {
        unsigned idx = g_fix_list[i];
        int b = idx >> 7;
        int j = idx & (HID - 1);

        const float* xr = x  + (size_t)b * INF;
        const float* wr = W1 + (size_t)j * INF;
        float a = 0.0f;
        for (int k = 0; k < INF; k++)
            a = fmaf(__ldg(&xr[k]), __ldg(&wr[k]), a);
        float curv = a + __ldg(&b1[j]);

        // permuted position: jw = j&31 = nt*8 + tg*2 + b0 -> pos = tg*8 + nt*2 + b0
        const int wordi = j >> 5;
        const int jw = j & 31;
        const int pos = ((jw >> 1) & 3) * 8 + (jw >> 3) * 2 + (jw & 1);
        const unsigned bit = 1u << pos;

        float m = 0.0f;
        for (int t = 0; t < TSTEPS; t++) {
            m = fmaf(m, DECAYF, curv);
            float s = (m > THRESHF) ? 1.0f : 0.0f;
            out_spk[(size_t)t * ((size_t)BATCH * HID) + idx] = s;
            unsigned* bp = &g_bits[((size_t)t * BATCH + b) * 4 + wordi];
            if (s != 0.0f) atomicOr(bp, bit);
            else           atomicAnd(bp, ~bit);
            m = (s != 0.0f) ? 0.0f : m;
        }
    }
}

// ---------------------------------------------------------------------------
// K3: c2 from bitpacked spikes (permuted layout), ascending-original-j fmaf
// chain -> bitwise identical to the proven R5 k3. One thread per (t,b) row.
// ---------------------------------------------------------------------------
__global__ __launch_bounds__(256) void k3_bits(const float* __restrict__ W2)
{
    __shared__ float W2t[HID][12];
    const int tid = threadIdx.x;
    for (int i = tid; i < HID * NCLS; i += 256) {
        int j = i / NCLS;
        int o = i - j * NCLS;
        W2t[j][o] = W2[o * HID + j];
    }
    __syncthreads();

    const size_t row = (size_t)blockIdx.x * 256 + tid;   // over TSTEPS*BATCH
    uint4 bw = *reinterpret_cast<const uint4*>(&g_bits[row * 4]);
    unsigned wds[4] = {bw.x, bw.y, bw.z, bw.w};

    float acc[NCLS];
    #pragma unroll
    for (int o = 0; o < NCLS; o++) acc[o] = 0.0f;

    #pragma unroll
    for (int w = 0; w < 4; w++) {
        unsigned word = wds[w];
        #pragma unroll
        for (int jw = 0; jw < 32; jw++) {       // ascending original j
            const int pos = ((jw >> 1) & 3) * 8 + (jw >> 3) * 2 + (jw & 1);
            float s = ((word >> pos) & 1u) ? 1.0f : 0.0f;
            const float* wr = W2t[w * 32 + jw];
            float4 w0 = *reinterpret_cast<const float4*>(wr);
            float4 w1 = *reinterpret_cast<const float4*>(wr + 4);
            float2 w2 = *reinterpret_cast<const float2*>(wr + 8);
            acc[0] = fmaf(s, w0.x, acc[0]);
            acc[1] = fmaf(s, w0.y, acc[1]);
            acc[2] = fmaf(s, w0.z, acc[2]);
            acc[3] = fmaf(s, w0.w, acc[3]);
            acc[4] = fmaf(s, w1.x, acc[4]);
            acc[5] = fmaf(s, w1.y, acc[5]);
            acc[6] = fmaf(s, w1.z, acc[6]);
            acc[7] = fmaf(s, w1.w, acc[7]);
            acc[8] = fmaf(s, w2.x, acc[8]);
            acc[9] = fmaf(s, w2.y, acc[9]);
        }
    }

    float* cp = &g_c2[row * NCLS];
    #pragma unroll
    for (int o = 0; o < NCLS; o++) cp[o] = acc[o];
}

// ---------------------------------------------------------------------------
__global__ __launch_bounds__(256) void k4_lif2(
    const float* __restrict__ b2, float* __restrict__ outp)
{
    const int id = blockIdx.x * blockDim.x + threadIdx.x;
    const int o = id % NCLS;
    const float bias = __ldg(&b2[o]);

    float mem = 0.0f, acc = 0.0f;
    #pragma unroll
    for (int t = 0; t < TSTEPS; t++) {
        float v = fmaf(mem, DECAYF, g_c2[(size_t)t * (BATCH * NCLS) + id]);
        v = v + bias;
        float s = (v > THRESHF) ? 1.0f : 0.0f;
        acc += s;
        mem = (s != 0.0f) ? 0.0f : v;
    }
    outp[id] = acc;
}

// ---------------------------------------------------------------------------
extern "C" void kernel_launch(void* const* d_in, const int* in_sizes, int n_in,
                              void* d_out, int out_size)
{
    const float* x  = (const float*)d_in[0];
    const float* W1 = (const float*)d_in[1];
    const float* b1 = (const float*)d_in[2];
    const float* W2 = (const float*)d_in[3];
    const float* b2 = (const float*)d_in[4];
    float* out = (float*)d_out;

    float* out_output = out;
    float* out_spk    = out + (size_t)BATCH * NCLS;

    k0_init<<<(HID * INF + 255) / 256, 256>>>(W1);
    k1_mma<<<BATCH / 64, 256>>>(x, b1, out_spk);
    k1_fixup<<<256, 128>>>(x, W1, b1, out_spk);
    k3_bits<<<(TSTEPS * BATCH) / 256, 256>>>(W2);
    k4_lif2<<<(BATCH * NCLS) / 256, 256>>>(b2, out_output);
}